// round 9
// baseline (speedup 1.0000x reference)
#include <cuda_runtime.h>
#include <cstdint>
#include <math.h>

#define B_SZ 4096
#define T_SZ 2048
#define WARPS_PER_BLOCK 4
#define NBLOCKS (B_SZ / WARPS_PER_BLOCK)   // 1024
#define PF 4                                // float4 loads per group (per lane)
#define NGRP 8                              // groups of 4 windows: 8*4*64 = 2048 steps
#define STAGES 4                            // smem ring depth
#define DT 0.01f

// Per-block partials: (sum_wq2, sum_wp2, penalty_sum, unused)
__device__ float4 g_blk[NBLOCKS];
__device__ unsigned g_cnt = 0;

struct M2f { float a, b, c, d; };   // [[a,b],[c,d]]

__device__ __forceinline__ M2f m2mul(const M2f& X, const M2f& Y) {
    M2f r;
    r.a = fmaf(X.a, Y.a, X.b * Y.c);
    r.b = fmaf(X.a, Y.b, X.b * Y.d);
    r.c = fmaf(X.c, Y.a, X.d * Y.c);
    r.d = fmaf(X.c, Y.b, X.d * Y.d);
    return r;
}

__device__ __forceinline__ void cp16(unsigned int dst, const float4* src) {
    asm volatile("cp.async.cg.shared.global [%0], [%1], 16;" :: "r"(dst), "l"(src));
}
__device__ __forceinline__ void cp_commit() {
    asm volatile("cp.async.commit_group;" ::: "memory");
}
template<int N> __device__ __forceinline__ void cp_wait() {
    asm volatile("cp.async.wait_group %0;" :: "n"(N) : "memory");
}

__global__ void __launch_bounds__(WARPS_PER_BLOCK * 32)
rollout_kernel(const float4* __restrict__ x4, const float* __restrict__ y_pred,
               float* __restrict__ out)
{
    // smem ring: [warp][stage][group-slot j][lane]  (32 KB)
    __shared__ float4 stg[WARPS_PER_BLOCK][STAGES][PF][32];
    __shared__ float s_q[WARPS_PER_BLOCK], s_p[WARPS_PER_BLOCK], s_n[WARPS_PER_BLOCK];
    __shared__ double fsq[128], fsp[128], fsn[128];
    __shared__ bool isLast;

    const int wid  = threadIdx.x >> 5;
    const int lane = threadIdx.x & 31;
    const int bidx = blockIdx.x * WARPS_PER_BLOCK + wid;   // batch index

    const float4* xr = x4 + (size_t)bidx * (T_SZ / 2);
    const unsigned int sbase =
        (unsigned int)__cvta_generic_to_shared(&stg[wid][0][0][lane]);

    // ---- start the async stream immediately: stages 0..2 (12 LDGSTS/thread) ----
    #pragma unroll
    for (int g = 0; g < STAGES - 1; ++g) {
        #pragma unroll
        for (int j = 0; j < PF; ++j)
            cp16(sbase + (unsigned int)(((g * PF + j) * 32) * 16),
                 &xr[(g * PF + j) * 32 + lane]);
        cp_commit();
    }
    const float4 x0 = __ldg(&xr[0]);              // (q0, pi0, q1-true, pi1-true)

    // ---- prologue (overlaps with in-flight cp.async) ----
    const float y0 = __ldg(&y_pred[bidx * 3 + 0]);
    const float y1 = __ldg(&y_pred[bidx * 3 + 1]);
    const float y2 = __ldg(&y_pred[bidx * 3 + 2]);
    const float m   = y0 + 0.1f;
    const float dtm = DT / m;
    const float dtk = DT * y1;
    const float dtl = DT * y2;

    // fp32 step operator: q' = q + dtm*pi ; pi' = -dtk*q' + (1-dtl)*pi
    M2f A;
    A.a = 1.0f;   A.b = dtm;
    A.c = -dtk;   A.d = 1.0f - dtl - dtk * dtm;

    // P = (A^2)^lane via binexp; chain ends with cur = A^64.
    M2f cur = m2mul(A, A);                        // A^2
    M2f P; P.a = 1.0f; P.b = 0.0f; P.c = 0.0f; P.d = 1.0f;
    unsigned e = (unsigned)lane;
    #pragma unroll
    for (int i = 0; i < 5; ++i) {
        if (e & 1u) P = m2mul(P, cur);
        e >>= 1;
        cur = m2mul(cur, cur);                    // ends at A^64
    }
    const M2f M64 = cur;

    // Seed this lane's state at t = 2*lane
    float q  = fmaf(P.a, x0.x, P.b * x0.y);
    float pi = fmaf(P.c, x0.x, P.d * x0.y);

    float w0 = (float)(T_SZ - 2 * lane);
    float accq = 0.0f, accp = 0.0f;

    // ---- main loop: smem ring, 3 stages always in flight, fully unrolled ----
    #pragma unroll
    for (int g = 0; g < NGRP; ++g) {
        // ensure group g's data has landed (allow ≤2 later groups pending)
        if (g <= NGRP - 3)      cp_wait<2>();
        else if (g == NGRP - 2) cp_wait<1>();
        else                    cp_wait<0>();

        // refill: issue group g+3 into the slot freed by group g-1
        if (g + STAGES - 1 < NGRP) {
            const int gn = g + STAGES - 1;
            const int s  = gn & (STAGES - 1);
            #pragma unroll
            for (int j = 0; j < PF; ++j)
                cp16(sbase + (unsigned int)(((s * PF + j) * 32) * 16),
                     &xr[(gn * PF + j) * 32 + lane]);
            cp_commit();
        }

        const int sc = g & (STAGES - 1);
        #pragma unroll
        for (int j = 0; j < PF; ++j) {
            const float4 xv = stg[wid][sc][j][lane];

            const float dq0 = q  - xv.x;
            const float dp0 = pi - xv.y;
            accq = fmaf(w0 * dq0, dq0, accq);
            accp = fmaf(w0 * dp0, dp0, accp);

            // exact fp32 step for t+1
            const float q1  = fmaf(dtm, pi, q);
            const float pi1 = fmaf(-dtk, q1, fmaf(-dtl, pi, pi));
            const float dq1 = q1  - xv.z;
            const float dp1 = pi1 - xv.w;
            const float w1 = w0 - 1.0f;
            accq = fmaf(w1 * dq1, dq1, accq);
            accp = fmaf(w1 * dp1, dp1, accp);

            // advance window state by A^64
            const float qn  = fmaf(M64.a, q, M64.b * pi);
            const float pin = fmaf(M64.c, q, M64.d * pi);
            q = qn; pi = pin;
            w0 -= 64.0f;
        }
    }

    // warp reduction
    #pragma unroll
    for (int off = 16; off; off >>= 1) {
        accq += __shfl_down_sync(0xffffffffu, accq, off);
        accp += __shfl_down_sync(0xffffffffu, accp, off);
    }

    if (lane == 0) {
        float pen = 0.0f;
        if (y0 < 0.0f) pen += expf(-10.0f * y0);
        if (y1 < 0.0f) pen += expf(-10.0f * y1);
        if (y2 < 0.0f) pen += expf(-10.0f * y2);
        s_q[wid] = accq; s_p[wid] = accp; s_n[wid] = pen;
    }
    __syncthreads();

    if (threadIdx.x == 0) {
        float bq = 0.0f, bp = 0.0f, bn = 0.0f;
        #pragma unroll
        for (int i = 0; i < WARPS_PER_BLOCK; ++i) { bq += s_q[i]; bp += s_p[i]; bn += s_n[i]; }
        g_blk[blockIdx.x] = make_float4(bq, bp, bn, 0.0f);
        __threadfence();
        unsigned c = atomicAdd(&g_cnt, 1u);
        isLast = (c == NBLOCKS - 1);
    }
    __syncthreads();

    // Last block: deterministic fixed-order final reduction over 1024 partials
    if (isLast) {
        const int t = threadIdx.x;          // 0..127
        double aq = 0.0, ap = 0.0, an = 0.0;
        #pragma unroll
        for (int i = 0; i < NBLOCKS / 128; ++i) {     // 8 independent loads
            const float4 v = __ldcg(&g_blk[t + 128 * i]);
            aq += (double)v.x; ap += (double)v.y; an += (double)v.z;
        }
        fsq[t] = aq; fsp[t] = ap; fsn[t] = an;
        __syncthreads();
        #pragma unroll
        for (int off = 64; off; off >>= 1) {
            if (t < off) { fsq[t] += fsq[t + off]; fsp[t] += fsp[t + off]; fsn[t] += fsn[t + off]; }
            __syncthreads();
        }
        if (t == 0) {
            double rq = sqrt(fsq[0] / (double)B_SZ);
            double rp = sqrt(fsp[0] / (double)B_SZ);
            rq = fmin(rq, 1.0e15);
            rp = fmin(rp, 1.0e15);
            double pen = fsn[0] / (double)(B_SZ * 3);
            pen = fmin(fmax(pen, 0.0), 1000.0);
            out[0] = (float)(0.5 * (rq + rp) + pen);
            g_cnt = 0;                 // reset for next graph replay
        }
    }
}

extern "C" void kernel_launch(void* const* d_in, const int* in_sizes, int n_in,
                              void* d_out, int out_size)
{
    int xi = 0, yi = 1;
    if (n_in >= 2 && in_sizes[0] == B_SZ * 3) { xi = 1; yi = 0; }
    const float4* x4     = (const float4*)d_in[xi];
    const float*  y_pred = (const float*)d_in[yi];
    float* out = (float*)d_out;

    rollout_kernel<<<NBLOCKS, WARPS_PER_BLOCK * 32>>>(x4, y_pred, out);
}

// round 11
// speedup vs baseline: 1.1005x; 1.1005x over previous
#include <cuda_runtime.h>
#include <cstdint>
#include <math.h>

#define B_SZ 4096
#define T_SZ 2048
#define WARPS_PER_BLOCK 4
#define NBLOCKS (B_SZ / WARPS_PER_BLOCK)   // 1024
#define NWIN 32                             // 32 windows of 64 timesteps per warp
#define PF 8                                // prefetch group size (float4 loads)
#define NGRP (NWIN / PF)                    // 4 groups
#define DT 0.01f

// Per-block partials: (sum_wq2, sum_wp2, penalty_sum, unused)
__device__ float4 g_blk[NBLOCKS];
__device__ unsigned g_cnt = 0;

struct M2f { float a, b, c, d; };   // [[a,b],[c,d]]

__device__ __forceinline__ M2f m2mul(const M2f& X, const M2f& Y) {
    M2f r;
    r.a = fmaf(X.a, Y.a, X.b * Y.c);
    r.b = fmaf(X.a, Y.b, X.b * Y.d);
    r.c = fmaf(X.c, Y.a, X.d * Y.c);
    r.d = fmaf(X.c, Y.b, X.d * Y.d);
    return r;
}

// L2 evict-last policy register (created once per thread).
__device__ __forceinline__ uint64_t mk_policy_el() {
    uint64_t pol;
    asm volatile("createpolicy.fractional.L2::evict_last.b64 %0, 1.0;" : "=l"(pol));
    return pol;
}

// Streaming load with L2 evict-last hint: pin x in L2 across graph replays.
__device__ __forceinline__ float4 ldg_el(const float4* p, uint64_t pol) {
    float4 v;
    asm volatile("ld.global.nc.L2::cache_hint.v4.f32 {%0,%1,%2,%3}, [%4], %5;"
                 : "=f"(v.x), "=f"(v.y), "=f"(v.z), "=f"(v.w)
                 : "l"(p), "l"(pol));
    return v;
}

__global__ void __launch_bounds__(WARPS_PER_BLOCK * 32)
rollout_kernel(const float4* __restrict__ x4, const float* __restrict__ y_pred,
               float* __restrict__ out)
{
    __shared__ float s_q[WARPS_PER_BLOCK], s_p[WARPS_PER_BLOCK], s_n[WARPS_PER_BLOCK];
    __shared__ double fsq[128], fsp[128], fsn[128];
    __shared__ bool isLast;

    const int wid  = threadIdx.x >> 5;
    const int lane = threadIdx.x & 31;
    const int bidx = blockIdx.x * WARPS_PER_BLOCK + wid;   // batch index

    const float4* xr = x4 + (size_t)bidx * (T_SZ / 2);
    const uint64_t pol = mk_policy_el();

    // ---- start the memory stream immediately: prefetch group 0 (8 LDG.128) ----
    float4 bufA[PF], bufB[PF];
    #pragma unroll
    for (int j = 0; j < PF; ++j) bufA[j] = ldg_el(&xr[j * 32 + lane], pol);
    const float4 x0 = ldg_el(&xr[0], pol);        // (q0, pi0, q1-true, pi1-true)

    // ---- prologue (overlaps with in-flight loads) ----
    const float y0 = __ldg(&y_pred[bidx * 3 + 0]);
    const float y1 = __ldg(&y_pred[bidx * 3 + 1]);
    const float y2 = __ldg(&y_pred[bidx * 3 + 2]);
    const float m   = y0 + 0.1f;
    const float dtm = DT / m;
    const float dtk = DT * y1;
    const float dtl = DT * y2;

    // fp32 step operator: q' = q + dtm*pi ; pi' = -dtk*q' + (1-dtl)*pi
    M2f A;
    A.a = 1.0f;   A.b = dtm;
    A.c = -dtk;   A.d = 1.0f - dtl - dtk * dtm;

    // P = (A^2)^lane via binexp; chain ends with cur = A^64.
    M2f cur = m2mul(A, A);                        // A^2
    M2f P; P.a = 1.0f; P.b = 0.0f; P.c = 0.0f; P.d = 1.0f;
    unsigned e = (unsigned)lane;
    #pragma unroll
    for (int i = 0; i < 5; ++i) {
        if (e & 1u) P = m2mul(P, cur);
        e >>= 1;
        cur = m2mul(cur, cur);                    // ends at A^64
    }
    const M2f M64 = cur;

    // Seed this lane's state at t = 2*lane
    float q  = fmaf(P.a, x0.x, P.b * x0.y);
    float pi = fmaf(P.c, x0.x, P.d * x0.y);

    float w0 = (float)(T_SZ - 2 * lane);
    float accq = 0.0f, accp = 0.0f;

    // ---- main loop: double-buffered, 8-deep, fully unrolled ----
    #pragma unroll
    for (int g = 0; g < NGRP; ++g) {
        float4* curb = (g & 1) ? bufB : bufA;
        float4* nxtb = (g & 1) ? bufA : bufB;

        if (g < NGRP - 1) {
            #pragma unroll
            for (int j = 0; j < PF; ++j)
                nxtb[j] = ldg_el(&xr[((g + 1) * PF + j) * 32 + lane], pol);
        }

        #pragma unroll
        for (int j = 0; j < PF; ++j) {
            const float4 xv = curb[j];

            const float dq0 = q  - xv.x;
            const float dp0 = pi - xv.y;
            accq = fmaf(w0 * dq0, dq0, accq);
            accp = fmaf(w0 * dp0, dp0, accp);

            // exact fp32 step for t+1
            const float q1  = fmaf(dtm, pi, q);
            const float pi1 = fmaf(-dtk, q1, fmaf(-dtl, pi, pi));
            const float dq1 = q1  - xv.z;
            const float dp1 = pi1 - xv.w;
            const float w1 = w0 - 1.0f;
            accq = fmaf(w1 * dq1, dq1, accq);
            accp = fmaf(w1 * dp1, dp1, accp);

            // advance window state by A^64
            const float qn  = fmaf(M64.a, q, M64.b * pi);
            const float pin = fmaf(M64.c, q, M64.d * pi);
            q = qn; pi = pin;
            w0 -= 64.0f;
        }
    }

    // warp reduction
    #pragma unroll
    for (int off = 16; off; off >>= 1) {
        accq += __shfl_down_sync(0xffffffffu, accq, off);
        accp += __shfl_down_sync(0xffffffffu, accp, off);
    }

    if (lane == 0) {
        float pen = 0.0f;
        if (y0 < 0.0f) pen += expf(-10.0f * y0);
        if (y1 < 0.0f) pen += expf(-10.0f * y1);
        if (y2 < 0.0f) pen += expf(-10.0f * y2);
        s_q[wid] = accq; s_p[wid] = accp; s_n[wid] = pen;
    }
    __syncthreads();

    if (threadIdx.x == 0) {
        float bq = 0.0f, bp = 0.0f, bn = 0.0f;
        #pragma unroll
        for (int i = 0; i < WARPS_PER_BLOCK; ++i) { bq += s_q[i]; bp += s_p[i]; bn += s_n[i]; }
        g_blk[blockIdx.x] = make_float4(bq, bp, bn, 0.0f);
        __threadfence();
        unsigned c = atomicAdd(&g_cnt, 1u);
        isLast = (c == NBLOCKS - 1);
    }
    __syncthreads();

    // Last block: deterministic fixed-order final reduction over 1024 partials
    if (isLast) {
        const int t = threadIdx.x;          // 0..127
        double aq = 0.0, ap = 0.0, an = 0.0;
        #pragma unroll
        for (int i = 0; i < NBLOCKS / 128; ++i) {     // 8 independent loads
            const float4 v = __ldcg(&g_blk[t + 128 * i]);
            aq += (double)v.x; ap += (double)v.y; an += (double)v.z;
        }
        fsq[t] = aq; fsp[t] = ap; fsn[t] = an;
        __syncthreads();
        #pragma unroll
        for (int off = 64; off; off >>= 1) {
            if (t < off) { fsq[t] += fsq[t + off]; fsp[t] += fsp[t + off]; fsn[t] += fsn[t + off]; }
            __syncthreads();
        }
        if (t == 0) {
            double rq = sqrt(fsq[0] / (double)B_SZ);
            double rp = sqrt(fsp[0] / (double)B_SZ);
            rq = fmin(rq, 1.0e15);
            rp = fmin(rp, 1.0e15);
            double pen = fsn[0] / (double)(B_SZ * 3);
            pen = fmin(fmax(pen, 0.0), 1000.0);
            out[0] = (float)(0.5 * (rq + rp) + pen);
            g_cnt = 0;                 // reset for next graph replay
        }
    }
}

extern "C" void kernel_launch(void* const* d_in, const int* in_sizes, int n_in,
                              void* d_out, int out_size)
{
    int xi = 0, yi = 1;
    if (n_in >= 2 && in_sizes[0] == B_SZ * 3) { xi = 1; yi = 0; }
    const float4* x4     = (const float4*)d_in[xi];
    const float*  y_pred = (const float*)d_in[yi];
    float* out = (float*)d_out;

    rollout_kernel<<<NBLOCKS, WARPS_PER_BLOCK * 32>>>(x4, y_pred, out);
}

// round 12
// speedup vs baseline: 1.1483x; 1.0435x over previous
#include <cuda_runtime.h>
#include <cstdint>
#include <math.h>

#define B_SZ 4096
#define T_SZ 2048
#define WARPS_PER_BLOCK 4
#define NBLOCKS (B_SZ / WARPS_PER_BLOCK)   // 1024
#define NWIN 16                             // 16 windows of 128 timesteps per warp
#define PF 4                                // prefetch group size (256-bit loads)
#define NGRP (NWIN / PF)                    // 4 groups
#define DT 0.01f

// Per-block partials: (sum_wq2, sum_wp2, penalty_sum, unused)
__device__ float4 g_blk[NBLOCKS];
__device__ unsigned g_cnt = 0;

struct M2f { float a, b, c, d; };   // [[a,b],[c,d]]

__device__ __forceinline__ M2f m2mul(const M2f& X, const M2f& Y) {
    M2f r;
    r.a = fmaf(X.a, Y.a, X.b * Y.c);
    r.b = fmaf(X.a, Y.b, X.b * Y.d);
    r.c = fmaf(X.c, Y.a, X.d * Y.c);
    r.d = fmaf(X.c, Y.b, X.d * Y.d);
    return r;
}

// 256-bit global load (sm_100a): 8 floats = 4 timesteps (q,pi pairs).
__device__ __forceinline__ void ldg256(const float* p, float* v) {
    unsigned r0, r1, r2, r3, r4, r5, r6, r7;
    asm volatile("ld.global.nc.v8.b32 {%0,%1,%2,%3,%4,%5,%6,%7}, [%8];"
                 : "=r"(r0), "=r"(r1), "=r"(r2), "=r"(r3),
                   "=r"(r4), "=r"(r5), "=r"(r6), "=r"(r7)
                 : "l"(p));
    v[0] = __uint_as_float(r0); v[1] = __uint_as_float(r1);
    v[2] = __uint_as_float(r2); v[3] = __uint_as_float(r3);
    v[4] = __uint_as_float(r4); v[5] = __uint_as_float(r5);
    v[6] = __uint_as_float(r6); v[7] = __uint_as_float(r7);
}

__global__ void __launch_bounds__(WARPS_PER_BLOCK * 32)
rollout_kernel(const float* __restrict__ x, const float* __restrict__ y_pred,
               float* __restrict__ out)
{
    __shared__ float s_q[WARPS_PER_BLOCK], s_p[WARPS_PER_BLOCK], s_n[WARPS_PER_BLOCK];
    __shared__ double fsq[128], fsp[128], fsn[128];
    __shared__ bool isLast;

    const int wid  = threadIdx.x >> 5;
    const int lane = threadIdx.x & 31;
    const int bidx = blockIdx.x * WARPS_PER_BLOCK + wid;   // batch index

    // batch row, indexed in 32-byte (8-float) units: unit u = floats [8u, 8u+8)
    const float* xr = x + (size_t)bidx * (T_SZ * 2);

    // ---- start the memory stream immediately: prefetch group 0 (4 LDG.256) ----
    float bufA[PF][8], bufB[PF][8];
    #pragma unroll
    for (int j = 0; j < PF; ++j) ldg256(xr + (size_t)(j * 32 + lane) * 8, bufA[j]);
    const float q0t = __ldg(&xr[0]);
    const float p0t = __ldg(&xr[1]);

    // ---- prologue (overlaps with in-flight loads) ----
    const float y0 = __ldg(&y_pred[bidx * 3 + 0]);
    const float y1 = __ldg(&y_pred[bidx * 3 + 1]);
    const float y2 = __ldg(&y_pred[bidx * 3 + 2]);
    const float m   = y0 + 0.1f;
    const float dtm = DT / m;
    const float dtk = DT * y1;
    const float dtl = DT * y2;

    // fp32 step operator: q' = q + dtm*pi ; pi' = -dtk*q' + (1-dtl)*pi
    M2f A;
    A.a = 1.0f;   A.b = dtm;
    A.c = -dtk;   A.d = 1.0f - dtl - dtk * dtm;

    // P = (A^4)^lane via binexp; squaring ladder ends at cur = A^128.
    M2f cur = m2mul(A, A);                        // A^2
    cur = m2mul(cur, cur);                        // A^4
    M2f P; P.a = 1.0f; P.b = 0.0f; P.c = 0.0f; P.d = 1.0f;
    unsigned e = (unsigned)lane;
    #pragma unroll
    for (int i = 0; i < 5; ++i) {
        if (e & 1u) P = m2mul(P, cur);
        e >>= 1;
        cur = m2mul(cur, cur);                    // ends at A^128
    }
    const M2f M128 = cur;

    // Seed this lane's state at t = 4*lane
    float q  = fmaf(P.a, q0t, P.b * p0t);
    float pi = fmaf(P.c, q0t, P.d * p0t);

    float w0 = (float)(T_SZ - 4 * lane);          // weight at t = 4*lane
    float accq = 0.0f, accp = 0.0f;

    // ---- main loop: double-buffered 256-bit stream, fully unrolled ----
    #pragma unroll
    for (int g = 0; g < NGRP; ++g) {
        float (*curb)[8] = (g & 1) ? bufB : bufA;
        float (*nxtb)[8] = (g & 1) ? bufA : bufB;

        if (g < NGRP - 1) {
            #pragma unroll
            for (int j = 0; j < PF; ++j)
                ldg256(xr + (size_t)(((g + 1) * PF + j) * 32 + lane) * 8, nxtb[j]);
        }

        #pragma unroll
        for (int j = 0; j < PF; ++j) {
            const float* xv = curb[j];

            float qq = q, pp = pi;
            float w = w0;
            #pragma unroll
            for (int s = 0; s < 4; ++s) {
                const float dq = qq - xv[2 * s];
                const float dp = pp - xv[2 * s + 1];
                accq = fmaf(w * dq, dq, accq);
                accp = fmaf(w * dp, dp, accp);
                w -= 1.0f;
                if (s < 3) {
                    qq = fmaf(dtm, pp, qq);                    // exact fp32 step
                    pp = fmaf(-dtk, qq, fmaf(-dtl, pp, pp));
                }
            }

            // advance window state by A^128
            const float qn  = fmaf(M128.a, q, M128.b * pi);
            const float pin = fmaf(M128.c, q, M128.d * pi);
            q = qn; pi = pin;
            w0 -= 128.0f;
        }
    }

    // warp reduction
    #pragma unroll
    for (int off = 16; off; off >>= 1) {
        accq += __shfl_down_sync(0xffffffffu, accq, off);
        accp += __shfl_down_sync(0xffffffffu, accp, off);
    }

    if (lane == 0) {
        float pen = 0.0f;
        if (y0 < 0.0f) pen += expf(-10.0f * y0);
        if (y1 < 0.0f) pen += expf(-10.0f * y1);
        if (y2 < 0.0f) pen += expf(-10.0f * y2);
        s_q[wid] = accq; s_p[wid] = accp; s_n[wid] = pen;
    }
    __syncthreads();

    if (threadIdx.x == 0) {
        float bq = 0.0f, bp = 0.0f, bn = 0.0f;
        #pragma unroll
        for (int i = 0; i < WARPS_PER_BLOCK; ++i) { bq += s_q[i]; bp += s_p[i]; bn += s_n[i]; }
        g_blk[blockIdx.x] = make_float4(bq, bp, bn, 0.0f);
        __threadfence();
        unsigned c = atomicAdd(&g_cnt, 1u);
        isLast = (c == NBLOCKS - 1);
    }
    __syncthreads();

    // Last block: deterministic fixed-order final reduction over 1024 partials
    if (isLast) {
        const int t = threadIdx.x;          // 0..127
        double aq = 0.0, ap = 0.0, an = 0.0;
        #pragma unroll
        for (int i = 0; i < NBLOCKS / 128; ++i) {     // 8 independent loads
            const float4 v = __ldcg(&g_blk[t + 128 * i]);
            aq += (double)v.x; ap += (double)v.y; an += (double)v.z;
        }
        fsq[t] = aq; fsp[t] = ap; fsn[t] = an;
        __syncthreads();
        #pragma unroll
        for (int off = 64; off; off >>= 1) {
            if (t < off) { fsq[t] += fsq[t + off]; fsp[t] += fsp[t + off]; fsn[t] += fsn[t + off]; }
            __syncthreads();
        }
        if (t == 0) {
            double rq = sqrt(fsq[0] / (double)B_SZ);
            double rp = sqrt(fsp[0] / (double)B_SZ);
            rq = fmin(rq, 1.0e15);
            rp = fmin(rp, 1.0e15);
            double pen = fsn[0] / (double)(B_SZ * 3);
            pen = fmin(fmax(pen, 0.0), 1000.0);
            out[0] = (float)(0.5 * (rq + rp) + pen);
            g_cnt = 0;                 // reset for next graph replay
        }
    }
}

extern "C" void kernel_launch(void* const* d_in, const int* in_sizes, int n_in,
                              void* d_out, int out_size)
{
    int xi = 0, yi = 1;
    if (n_in >= 2 && in_sizes[0] == B_SZ * 3) { xi = 1; yi = 0; }
    const float* x       = (const float*)d_in[xi];
    const float* y_pred  = (const float*)d_in[yi];
    float* out = (float*)d_out;

    rollout_kernel<<<NBLOCKS, WARPS_PER_BLOCK * 32>>>(x, y_pred, out);
}